// round 14
// baseline (speedup 1.0000x reference)
#include <cuda_runtime.h>
#include <cuda_fp16.h>
#include <math.h>

#define NB 4
#define CC 256
#define HEADS 4
#define DH 64
#define LL 4096
#define GROUPS 32

// Scratch (allocation-free rule: __device__ globals)
__device__ __half g_qh[NB * HEADS * LL * DH];   // [n][h][l][d]
__device__ __half g_kh[NB * HEADS * LL * DH];   // [n][h][l][d]
__device__ __half g_vh[NB * HEADS * DH * LL];   // [n][h][d][l]
__device__ __half g_ao[NB * CC * LL];           // attn output, [c][l] fp16
__device__ __half g_wh[4 * CC * CC];            // fp16 Wq(*scale),Wk,Wv,Wp
__device__ float2 g_st[NB * CC];                // per-channel (a, b): xn = x*a + b

// ---------------------------------------------------------------------------
// helpers
// ---------------------------------------------------------------------------
__device__ __forceinline__ float ex2f(float x) {
    float r;
    asm("ex2.approx.ftz.f32 %0, %1;" : "=f"(r) : "f"(x));
    return r;
}
__device__ __forceinline__ unsigned h2_as_u32(__half2 h) {
    return *reinterpret_cast<unsigned*>(&h);
}
__device__ __forceinline__ void mma_f16(float* c, const unsigned* a,
                                        unsigned b0, unsigned b1) {
    asm volatile(
        "mma.sync.aligned.m16n8k16.row.col.f32.f16.f16.f32 "
        "{%0,%1,%2,%3}, {%4,%5,%6,%7}, {%8,%9}, {%0,%1,%2,%3};"
        : "+f"(c[0]), "+f"(c[1]), "+f"(c[2]), "+f"(c[3])
        : "r"(a[0]), "r"(a[1]), "r"(a[2]), "r"(a[3]), "r"(b0), "r"(b1));
}
__device__ __forceinline__ void ldsm_x4(unsigned& r0, unsigned& r1,
                                        unsigned& r2, unsigned& r3,
                                        unsigned saddr) {
    asm volatile("ldmatrix.sync.aligned.m8n8.x4.shared.b16 {%0,%1,%2,%3}, [%4];"
                 : "=r"(r0), "=r"(r1), "=r"(r2), "=r"(r3) : "r"(saddr));
}
__device__ __forceinline__ void ldsm_x4_t(unsigned& r0, unsigned& r1,
                                          unsigned& r2, unsigned& r3,
                                          unsigned saddr) {
    asm volatile("ldmatrix.sync.aligned.m8n8.x4.trans.shared.b16 {%0,%1,%2,%3}, [%4];"
                 : "=r"(r0), "=r"(r1), "=r"(r2), "=r"(r3) : "r"(saddr));
}
__device__ __forceinline__ void cp16(void* smem_dst, const void* gmem_src) {
    unsigned sa = (unsigned)__cvta_generic_to_shared(smem_dst);
    asm volatile("cp.async.ca.shared.global [%0], [%1], 16;"
                 :: "r"(sa), "l"(gmem_src) : "memory");
}

// ---------------------------------------------------------------------------
// Weight prep: fp16-round; Wq pre-scaled by dh^-0.5 * log2(e).
// ---------------------------------------------------------------------------
__global__ void wcvt_kernel(const float* __restrict__ Wq, const float* __restrict__ Wk,
                            const float* __restrict__ Wv, const float* __restrict__ Wp,
                            __half* __restrict__ wh) {
    const float qscale = 0.125f * 1.44269504088896340736f;
    int i4 = (blockIdx.x * 256 + threadIdx.x) * 4;
    {
        float4 w = *reinterpret_cast<const float4*>(&Wq[i4]);
        __half2 h01 = __floats2half2_rn(w.x * qscale, w.y * qscale);
        __half2 h23 = __floats2half2_rn(w.z * qscale, w.w * qscale);
        *reinterpret_cast<uint2*>(&wh[i4]) = make_uint2(h2_as_u32(h01), h2_as_u32(h23));
    }
    const float* src[3] = {Wk, Wv, Wp};
    #pragma unroll
    for (int m = 0; m < 3; m++) {
        float4 w = *reinterpret_cast<const float4*>(&src[m][i4]);
        __half2 h01 = __floats2half2_rn(w.x, w.y);
        __half2 h23 = __floats2half2_rn(w.z, w.w);
        *reinterpret_cast<uint2*>(&wh[(m + 1) * CC * CC + i4]) =
            make_uint2(h2_as_u32(h01), h2_as_u32(h23));
    }
}

// ---------------------------------------------------------------------------
// GroupNorm stats only: one block per (n, group), 1024 threads.
// Emits per-channel affine (a, b) with xn = x*a + b; normalize is fused
// into the QKV projection's X-tile load.
// ---------------------------------------------------------------------------
__global__ void __launch_bounds__(1024) gn_stats_kernel(
        const float* __restrict__ x, const float* __restrict__ gamma,
        const float* __restrict__ beta, float2* __restrict__ st) {
    int n = blockIdx.x >> 5;
    int g = blockIdx.x & 31;
    const float* xp = x + (size_t)(n * CC + g * 8) * LL;

    float s = 0.f, ss = 0.f;
    for (int i4 = threadIdx.x * 4; i4 < 8 * LL; i4 += 4096) {
        float4 v = *reinterpret_cast<const float4*>(&xp[i4]);
        s  += v.x + v.y + v.z + v.w;
        ss += v.x * v.x + v.y * v.y + v.z * v.z + v.w * v.w;
    }
    __shared__ float rs[1024], rss[1024];
    rs[threadIdx.x] = s; rss[threadIdx.x] = ss;
    __syncthreads();
    for (int o = 512; o > 0; o >>= 1) {
        if (threadIdx.x < o) {
            rs[threadIdx.x]  += rs[threadIdx.x + o];
            rss[threadIdx.x] += rss[threadIdx.x + o];
        }
        __syncthreads();
    }
    if (threadIdx.x < 8) {
        const float invN = 1.f / (8.f * LL);
        float mean = rs[0] * invN;
        float var  = rss[0] * invN - mean * mean;
        float inv  = rsqrtf(var + 1e-5f);
        int c = g * 8 + threadIdx.x;
        float a = inv * gamma[c];
        float b = beta[c] - mean * a;
        st[n * CC + c] = make_float2(a, b);
    }
}

// ---------------------------------------------------------------------------
// Fused GN-normalize + QKV projection, fp16 m16n8k16. X tile loaded f32,
// normalized (x*a+b) and fp16-rounded into smem. B-frags via ldmatrix.trans;
// Ws A-frags via ldmatrix. Outputs __half in attention layouts.
// ---------------------------------------------------------------------------
#define PX 72   // Xs row pad (halves), 144 B rows
#define PW 40   // Ws row pad (halves), 80 B rows

__global__ void __launch_bounds__(128) qkv_f16_kernel(
        const float* __restrict__ x, const float2* __restrict__ st,
        const __half* __restrict__ wh,
        __half* __restrict__ qh, __half* __restrict__ kh, __half* __restrict__ vh) {
    __shared__ __half Xs[32 * PX];
    __shared__ __half Ws[3][64 * PW];

    int n  = blockIdx.z;
    int o0 = blockIdx.y << 6;
    int l0 = blockIdx.x << 6;
    const float*  xb = x  + (size_t)n * CC * LL;
    const float2* sb = st + n * CC;

    int tid = threadIdx.x;
    int lane = tid & 31, w = tid >> 5;
    int g = lane >> 2, t4 = lane & 3;
    int quad = lane >> 3, r8 = lane & 7;

    unsigned xs_s = (unsigned)__cvta_generic_to_shared(Xs);
    unsigned ws_s[3];
    #pragma unroll
    for (int m = 0; m < 3; m++)
        ws_s[m] = (unsigned)__cvta_generic_to_shared(Ws[m]);
    unsigned offXB = (unsigned)(((quad & 1) * 8 + r8) * (PX * 2) + (quad >> 1) * 16);
    unsigned offWA = (unsigned)((w * 16 + (quad & 1) * 8 + r8) * (PW * 2) + (quad >> 1) * 16);

    float acc[3][8][4];
    #pragma unroll
    for (int m = 0; m < 3; m++)
        #pragma unroll
        for (int nt = 0; nt < 8; nt++)
            #pragma unroll
            for (int c = 0; c < 4; c++) acc[m][nt][c] = 0.f;

    for (int c0 = 0; c0 < CC; c0 += 32) {
        __syncthreads();
        // Xs: 32 rows x 64 halves, from f32 x with fused normalize.
        // 512 float4 chunks (4 l-values each) -> 4 iterations.
        #pragma unroll
        for (int r = 0; r < 4; r++) {
            int cix = r * 128 + tid;
            int row = cix >> 4, ch = (cix & 15) * 4;
            float2 ab = sb[c0 + row];
            float4 v = *reinterpret_cast<const float4*>(
                &xb[(size_t)(c0 + row) * LL + l0 + ch]);
            __half2 h01 = __floats2half2_rn(v.x * ab.x + ab.y, v.y * ab.x + ab.y);
            __half2 h23 = __floats2half2_rn(v.z * ab.x + ab.y, v.w * ab.x + ab.y);
            *reinterpret_cast<uint2*>(&Xs[row * PX + ch]) =
                make_uint2(h2_as_u32(h01), h2_as_u32(h23));
        }
        // Ws: per matrix 64 rows x 32 halves (16B chunks)
        #pragma unroll
        for (int m = 0; m < 3; m++) {
            const __half* Wm = wh + m * CC * CC;
            #pragma unroll
            for (int r = 0; r < 2; r++) {
                int cix = r * 128 + tid;
                int row = cix >> 2, ch = (cix & 3) * 8;
                *reinterpret_cast<float4*>(&Ws[m][row * PW + ch]) =
                    *reinterpret_cast<const float4*>(&Wm[(size_t)(o0 + row) * CC + c0 + ch]);
            }
        }
        __syncthreads();

        #pragma unroll
        for (int kt = 0; kt < 2; kt++) {
            unsigned a[3][4];
            #pragma unroll
            for (int m = 0; m < 3; m++)
                ldsm_x4(a[m][0], a[m][1], a[m][2], a[m][3], ws_s[m] + kt * 32 + offWA);
            #pragma unroll
            for (int ntp = 0; ntp < 4; ntp++) {
                unsigned b0, b1, b2, b3;
                ldsm_x4_t(b0, b1, b2, b3,
                          xs_s + kt * (16 * PX * 2) + ntp * 32 + offXB);
                #pragma unroll
                for (int m = 0; m < 3; m++) {
                    mma_f16(acc[m][2 * ntp],     a[m], b0, b1);
                    mma_f16(acc[m][2 * ntp + 1], a[m], b2, b3);
                }
            }
        }
    }

    int orow = o0 + w * 16 + g;
    int h = orow >> 6, d0 = orow & 63;
    size_t nhb = (size_t)(n * HEADS + h);
    __half* qd = qh + nhb * LL * DH;
    __half* kd = kh + nhb * LL * DH;
    __half* vd = vh + nhb * DH * LL;

    #pragma unroll
    for (int nt = 0; nt < 8; nt++) {
        int l = l0 + nt * 8 + 2 * t4;
        qd[(size_t)l * DH + d0]           = __float2half_rn(acc[0][nt][0]);
        qd[(size_t)(l + 1) * DH + d0]     = __float2half_rn(acc[0][nt][1]);
        qd[(size_t)l * DH + d0 + 8]       = __float2half_rn(acc[0][nt][2]);
        qd[(size_t)(l + 1) * DH + d0 + 8] = __float2half_rn(acc[0][nt][3]);
        kd[(size_t)l * DH + d0]           = __float2half_rn(acc[1][nt][0]);
        kd[(size_t)(l + 1) * DH + d0]     = __float2half_rn(acc[1][nt][1]);
        kd[(size_t)l * DH + d0 + 8]       = __float2half_rn(acc[1][nt][2]);
        kd[(size_t)(l + 1) * DH + d0 + 8] = __float2half_rn(acc[1][nt][3]);
        *reinterpret_cast<__half2*>(&vd[(size_t)d0 * LL + l]) =
            __floats2half2_rn(acc[2][nt][0], acc[2][nt][1]);
        *reinterpret_cast<__half2*>(&vd[(size_t)(d0 + 8) * LL + l]) =
            __floats2half2_rn(acc[2][nt][2], acc[2][nt][3]);
    }
}

// ---------------------------------------------------------------------------
// Output projection, fp16 m16n8k16, + bias, f32 out (d_out).
// ---------------------------------------------------------------------------
__global__ void __launch_bounds__(128) oproj_f16_kernel(
        const __half* __restrict__ ao, const __half* __restrict__ wh,
        const float* __restrict__ bias, float* __restrict__ out) {
    __shared__ __half Xs[32 * PX];
    __shared__ __half Ws[64 * PW];

    int n  = blockIdx.z;
    int o0 = blockIdx.y << 6;
    int l0 = blockIdx.x << 6;
    const __half* xb = ao + (size_t)n * CC * LL;

    int tid = threadIdx.x;
    int lane = tid & 31, w = tid >> 5;
    int g = lane >> 2, t4 = lane & 3;
    int quad = lane >> 3, r8 = lane & 7;

    unsigned xs_s = (unsigned)__cvta_generic_to_shared(Xs);
    unsigned ws_s = (unsigned)__cvta_generic_to_shared(Ws);
    unsigned offXB = (unsigned)(((quad & 1) * 8 + r8) * (PX * 2) + (quad >> 1) * 16);
    unsigned offWA = (unsigned)((w * 16 + (quad & 1) * 8 + r8) * (PW * 2) + (quad >> 1) * 16);

    float acc[8][4];
    #pragma unroll
    for (int nt = 0; nt < 8; nt++)
        #pragma unroll
        for (int c = 0; c < 4; c++) acc[nt][c] = 0.f;

    for (int c0 = 0; c0 < CC; c0 += 32) {
        __syncthreads();
        #pragma unroll
        for (int r = 0; r < 2; r++) {
            int cix = r * 128 + tid;
            int row = cix >> 3, ch = (cix & 7) * 8;
            *reinterpret_cast<float4*>(&Xs[row * PX + ch]) =
                *reinterpret_cast<const float4*>(&xb[(size_t)(c0 + row) * LL + l0 + ch]);
        }
        #pragma unroll
        for (int r = 0; r < 2; r++) {
            int cix = r * 128 + tid;
            int row = cix >> 2, ch = (cix & 3) * 8;
            *reinterpret_cast<float4*>(&Ws[row * PW + ch]) =
                *reinterpret_cast<const float4*>(&wh[(size_t)(o0 + row) * CC + c0 + ch]);
        }
        __syncthreads();

        #pragma unroll
        for (int kt = 0; kt < 2; kt++) {
            unsigned a[4];
            ldsm_x4(a[0], a[1], a[2], a[3], ws_s + kt * 32 + offWA);
            #pragma unroll
            for (int ntp = 0; ntp < 4; ntp++) {
                unsigned b0, b1, b2, b3;
                ldsm_x4_t(b0, b1, b2, b3,
                          xs_s + kt * (16 * PX * 2) + ntp * 32 + offXB);
                mma_f16(acc[2 * ntp],     a, b0, b1);
                mma_f16(acc[2 * ntp + 1], a, b2, b3);
            }
        }
    }

    int orow = o0 + w * 16 + g;
    float bb0 = bias[orow], bb1 = bias[orow + 8];
    float* op = out + (size_t)n * CC * LL;
    #pragma unroll
    for (int nt = 0; nt < 8; nt++) {
        size_t base = (size_t)orow * LL + l0 + nt * 8 + 2 * t4;
        *reinterpret_cast<float2*>(&op[base]) =
            make_float2(acc[nt][0] + bb0, acc[nt][1] + bb0);
        *reinterpret_cast<float2*>(&op[base + 8 * LL]) =
            make_float2(acc[nt][2] + bb1, acc[nt][3] + bb1);
    }
}

// ---------------------------------------------------------------------------
// Flash attention, fp16 mma m16n8k16, register-resident P. (R13 mainloop)
// ---------------------------------------------------------------------------
#define PH 72
#define NT (LL / 64)

__global__ void __launch_bounds__(128) attn_f16_kernel(
        const __half* __restrict__ q, const __half* __restrict__ k,
        const __half* __restrict__ v, __half* __restrict__ ao) {
    extern __shared__ __align__(16) char smc[];
    __half* Ks = reinterpret_cast<__half*>(smc);
    __half* Vs = Ks + 64 * PH;
    __half* Qs = Vs + 64 * PH;
    __half* Osh = reinterpret_cast<__half*>(smc);  // epilogue staging [d][i] pad PH

    int nh = blockIdx.y;
    int l0 = blockIdx.x << 6;
    const __half* qb = q + (size_t)nh * LL * DH;
    const __half* kb = k + (size_t)nh * LL * DH;
    const __half* vb = v + (size_t)nh * DH * LL;

    int tid  = threadIdx.x;
    int lane = tid & 31, w = tid >> 5;
    int g = lane >> 2, t4 = lane & 3;
    int row0 = w * 16 + g;
    int quad = lane >> 3, r8 = lane & 7;

    unsigned ks_s = (unsigned)__cvta_generic_to_shared(Ks);
    unsigned vs_s = (unsigned)__cvta_generic_to_shared(Vs);
    unsigned qs_s = (unsigned)__cvta_generic_to_shared(Qs);
    unsigned offB = (unsigned)(((quad >> 1) * 8 + r8) * (PH * 2) + (quad & 1) * 16);
    unsigned offA = (unsigned)((w * 16 + (quad & 1) * 8 + r8) * (PH * 2) + (quad >> 1) * 16);

    #pragma unroll
    for (int r = 0; r < 4; r++) {
        int cix = r * 128 + tid;
        int row = cix >> 3, c8 = (cix & 7) * 8;
        cp16(&Qs[row * PH + c8], &qb[(size_t)(l0 + row) * DH + c8]);
    }
    asm volatile("cp.async.commit_group;" ::: "memory");
    asm volatile("cp.async.wait_group 0;" ::: "memory");
    __syncthreads();

    unsigned qa[4][4];
    #pragma unroll
    for (int kt = 0; kt < 4; kt++)
        ldsm_x4(qa[kt][0], qa[kt][1], qa[kt][2], qa[kt][3], qs_s + kt * 32 + offA);

    float m0 = -INFINITY, m1 = -INFINITY, ls0 = 0.f, ls1 = 0.f;
    float o[8][4];
    #pragma unroll
    for (int nt = 0; nt < 8; nt++)
        #pragma unroll
        for (int c = 0; c < 4; c++) o[nt][c] = 0.f;

    for (int jt = 0; jt < NT; jt++) {
        int lk = jt << 6;
        #pragma unroll
        for (int r = 0; r < 4; r++) {
            int cix = r * 128 + tid;
            int row = cix >> 3, c8 = (cix & 7) * 8;
            cp16(&Ks[row * PH + c8], &kb[(size_t)(lk + row) * DH + c8]);
            cp16(&Vs[row * PH + c8], &vb[(size_t)row * LL + lk + c8]);
        }
        asm volatile("cp.async.commit_group;" ::: "memory");
        asm volatile("cp.async.wait_group 0;" ::: "memory");
        __syncthreads();

        float s[8][4];
        #pragma unroll
        for (int nt = 0; nt < 8; nt++)
            #pragma unroll
            for (int c = 0; c < 4; c++) s[nt][c] = 0.f;
        #pragma unroll
        for (int kt = 0; kt < 4; kt++) {
            #pragma unroll
            for (int ntp = 0; ntp < 4; ntp++) {
                unsigned b0, b1, b2, b3;
                ldsm_x4(b0, b1, b2, b3, ks_s + ntp * (16 * PH * 2) + kt * 32 + offB);
                mma_f16(s[2 * ntp],     qa[kt], b0, b1);
                mma_f16(s[2 * ntp + 1], qa[kt], b2, b3);
            }
        }

        float mx0 = -INFINITY, mx1 = -INFINITY;
        #pragma unroll
        for (int nt = 0; nt < 8; nt++) {
            mx0 = fmaxf(mx0, fmaxf(s[nt][0], s[nt][1]));
            mx1 = fmaxf(mx1, fmaxf(s[nt][2], s[nt][3]));
        }
        mx0 = fmaxf(mx0, __shfl_xor_sync(0xffffffffu, mx0, 1));
        mx0 = fmaxf(mx0, __shfl_xor_sync(0xffffffffu, mx0, 2));
        mx1 = fmaxf(mx1, __shfl_xor_sync(0xffffffffu, mx1, 1));
        mx1 = fmaxf(mx1, __shfl_xor_sync(0xffffffffu, mx1, 2));
        float mn0 = fmaxf(m0, mx0), mn1 = fmaxf(m1, mx1);
        float c0 = ex2f(m0 - mn0), c1 = ex2f(m1 - mn1);
        float rs0 = 0.f, rs1 = 0.f;
        unsigned pw0[8], pw1[8];
        #pragma unroll
        for (int nt = 0; nt < 8; nt++) {
            float p00 = ex2f(s[nt][0] - mn0);
            float p01 = ex2f(s[nt][1] - mn0);
            float p10 = ex2f(s[nt][2] - mn1);
            float p11 = ex2f(s[nt][3] - mn1);
            rs0 += p00 + p01;
            rs1 += p10 + p11;
            pw0[nt] = h2_as_u32(__floats2half2_rn(p00, p01));
            pw1[nt] = h2_as_u32(__floats2half2_rn(p10, p11));
        }
        rs0 += __shfl_xor_sync(0xffffffffu, rs0, 1);
        rs0 += __shfl_xor_sync(0xffffffffu, rs0, 2);
        rs1 += __shfl_xor_sync(0xffffffffu, rs1, 1);
        rs1 += __shfl_xor_sync(0xffffffffu, rs1, 2);
        ls0 = ls0 * c0 + rs0;
        ls1 = ls1 * c1 + rs1;
        m0 = mn0; m1 = mn1;
        #pragma unroll
        for (int nt = 0; nt < 8; nt++) {
            o[nt][0] *= c0; o[nt][1] *= c0;
            o[nt][2] *= c1; o[nt][3] *= c1;
        }

        #pragma unroll
        for (int kt = 0; kt < 4; kt++) {
            unsigned a[4] = {pw0[2 * kt], pw1[2 * kt], pw0[2 * kt + 1], pw1[2 * kt + 1]};
            #pragma unroll
            for (int ntp = 0; ntp < 4; ntp++) {
                unsigned b0, b1, b2, b3;
                ldsm_x4(b0, b1, b2, b3, vs_s + ntp * (16 * PH * 2) + kt * 32 + offB);
                mma_f16(o[2 * ntp],     a, b0, b1);
                mma_f16(o[2 * ntp + 1], a, b2, b3);
            }
        }
        __syncthreads();
    }

    float inv0 = 1.f / ls0, inv1 = 1.f / ls1;
    #pragma unroll
    for (int nt = 0; nt < 8; nt++) {
        int d = nt * 8 + 2 * t4;
        Osh[(d    ) * PH + row0]     = __float2half_rn(o[nt][0] * inv0);
        Osh[(d + 1) * PH + row0]     = __float2half_rn(o[nt][1] * inv0);
        Osh[(d    ) * PH + row0 + 8] = __float2half_rn(o[nt][2] * inv1);
        Osh[(d + 1) * PH + row0 + 8] = __float2half_rn(o[nt][3] * inv1);
    }
    __syncthreads();
    #pragma unroll
    for (int r = 0; r < 4; r++) {
        int cix = r * 128 + tid;
        int d = cix >> 3, i8 = (cix & 7) * 8;
        float4 val = *reinterpret_cast<const float4*>(&Osh[d * PH + i8]);
        *reinterpret_cast<float4*>(&ao[((size_t)(nh * 64 + d)) * LL + l0 + i8]) = val;
    }
}

// ---------------------------------------------------------------------------
extern "C" void kernel_launch(void* const* d_in, const int* in_sizes, int n_in,
                              void* d_out, int out_size) {
    const float* x     = (const float*)d_in[0];
    const float* gamma = (const float*)d_in[1];
    const float* beta  = (const float*)d_in[2];
    const float* Wq    = (const float*)d_in[3];
    const float* Wk    = (const float*)d_in[4];
    const float* Wv    = (const float*)d_in[5];
    const float* Wp    = (const float*)d_in[6];
    const float* bp    = (const float*)d_in[7];
    float* out = (float*)d_out;

    static __half *qh = nullptr, *kh, *vh, *ao, *wh;
    static float2* st;
    static size_t attn_smem = (size_t)(3 * 64 * PH) * sizeof(__half);  // 27648 B
    if (!qh) {
        cudaGetSymbolAddress((void**)&qh, g_qh);
        cudaGetSymbolAddress((void**)&kh, g_kh);
        cudaGetSymbolAddress((void**)&vh, g_vh);
        cudaGetSymbolAddress((void**)&ao, g_ao);
        cudaGetSymbolAddress((void**)&wh, g_wh);
        cudaGetSymbolAddress((void**)&st, g_st);
        cudaFuncSetAttribute(attn_f16_kernel,
                             cudaFuncAttributeMaxDynamicSharedMemorySize,
                             (int)attn_smem);
    }

    // Weight fp16 prep (+Wq scaling) + GroupNorm stats (independent)
    wcvt_kernel<<<CC * CC / (256 * 4), 256>>>(Wq, Wk, Wv, Wp, wh);
    gn_stats_kernel<<<NB * GROUPS, 1024>>>(x, gamma, beta, st);

    // Fused GN-normalize + QKV projection (fp16 tensor cores)
    dim3 pgrid(LL / 64, CC / 64, NB);
    qkv_f16_kernel<<<pgrid, 128>>>(x, st, wh, qh, kh, vh);

    // Flash attention (fp16 m16n8k16, register-resident P)
    attn_f16_kernel<<<dim3(LL / 64, NB * HEADS), 128, attn_smem>>>(qh, kh, vh, ao);

    // Output projection (+bias) straight into d_out (fp16 tensor cores)
    oproj_f16_kernel<<<pgrid, 128>>>(ao, wh + 3 * CC * CC, bp, out);
}